// round 15
// baseline (speedup 1.0000x reference)
#include <cuda_runtime.h>
#include <cuda_fp16.h>
#include <cstdint>

// Problem constants
#define B_WIN   4096
#define SEQ     49
#define NPAD    64
#define CDIM    384
#define HEADS   12
#define HDIM    32
#define NW      1024
#define MROWS   (B_WIN * SEQ)        // 200704
#define QKV_N   (3 * CDIM)           // 1152
#define QKV_U   (QKV_N / 2)          // 576 u32 per row
#define K16S    (CDIM / 16)          // 24 k16-subtiles
#define SCALE_F 0.17677669529663687f // 32^-0.5
#define LOG2E   1.4426950408889634f

// Scratch (static device globals)
__device__ uint32_t g_qkv[(size_t)MROWS * QKV_U];              // half2 rows (B_*N, 576)
__device__ uint32_t g_xa[(size_t)(MROWS / 16) * K16S * 128];   // x, A-tiled fp16
__device__ uint32_t g_att_t[(size_t)(MROWS / 16) * K16S * 128];// attn out, A-tiled fp16
__device__ uint32_t g_wqkv_t[(QKV_N / 16) * K16S * 128];       // B-tiled fp16 [n16][k16][lane][4]
__device__ uint32_t g_wproj_t[(CDIM / 16) * K16S * 128];
__device__ uint32_t g_biasp_h[HEADS * 2048];                   // fp16 bias*log2e, permuted, pad=-30000
__device__ uint32_t g_maskp_h[NW * 2048];                      // fp16 mask*log2e, permuted, pad=0

// ---------------------------------------------------------------------------
// Helpers
// ---------------------------------------------------------------------------
__device__ __forceinline__ uint32_t h2u(float a, float b) {
    __half2 h = __floats2half2_rn(a, b);
    return *(uint32_t*)&h;
}
__device__ __forceinline__ float ex2(float x) {
    float y;
    asm("ex2.approx.f32 %0, %1;" : "=f"(y) : "f"(x));
    return y;
}

__device__ __forceinline__ void mma_f16(float* c, const uint32_t* a, const uint32_t* b) {
    asm volatile(
        "mma.sync.aligned.m16n8k16.row.col.f32.f16.f16.f32 "
        "{%0,%1,%2,%3}, {%4,%5,%6,%7}, {%8,%9}, {%0,%1,%2,%3};\n"
        : "+f"(c[0]), "+f"(c[1]), "+f"(c[2]), "+f"(c[3])
        : "r"(a[0]), "r"(a[1]), "r"(a[2]), "r"(a[3]), "r"(b[0]), "r"(b[1]));
}

__device__ __forceinline__ void ldsm_x4(uint32_t* r, uint32_t addr) {
    asm volatile("ldmatrix.sync.aligned.m8n8.x4.shared.b16 {%0,%1,%2,%3}, [%4];"
                 : "=r"(r[0]), "=r"(r[1]), "=r"(r[2]), "=r"(r[3]) : "r"(addr));
}
__device__ __forceinline__ void ldsm_x4_t(uint32_t* r, uint32_t addr) {
    asm volatile("ldmatrix.sync.aligned.m8n8.x4.trans.shared.b16 {%0,%1,%2,%3}, [%4];"
                 : "=r"(r[0]), "=r"(r[1]), "=r"(r[2]), "=r"(r[3]) : "r"(addr));
}
__device__ __forceinline__ uint32_t sm2u(const void* p) {
    return (uint32_t)__cvta_generic_to_shared(p);
}

__device__ __forceinline__ void cp_async16(void* smem_dst, const void* gmem_src) {
    uint32_t s = (uint32_t)__cvta_generic_to_shared(smem_dst);
    asm volatile("cp.async.cg.shared.global [%0], [%1], 16;\n" :: "r"(s), "l"(gmem_src));
}
__device__ __forceinline__ void cp_async16z(void* smem_dst, const void* gmem_src, uint32_t src_sz) {
    uint32_t s = (uint32_t)__cvta_generic_to_shared(smem_dst);
    asm volatile("cp.async.cg.shared.global [%0], [%1], 16, %2;\n" :: "r"(s), "l"(gmem_src), "r"(src_sz));
}
__device__ __forceinline__ void cp_async_commit() {
    asm volatile("cp.async.commit_group;\n" ::: "memory");
}
template <int N>
__device__ __forceinline__ void cp_async_wait() {
    asm volatile("cp.async.wait_group %0;\n" :: "n"(N) : "memory");
}

// A-tiled fp16 u32 index for element pair (m, c..c+1), c even, K=384
__device__ __forceinline__ size_t a16_off(int m, int c) {
    int m16 = m >> 4, rr = m & 15, k16 = c >> 4, kc = c & 15;
    int lane = ((rr & 7) << 2) | ((kc & 7) >> 1);
    int w = (rr >> 3) | ((kc >> 3) << 1);
    return (((size_t)m16 * K16S + k16) * 32 + lane) * 4 + w;
}

// ---------------------------------------------------------------------------
// Merged cvt_x + prep (block-range partitioned)
// ---------------------------------------------------------------------------
#define CVT_BLKS 37632    // (MROWS/16)*K16S*32 / 256
#define PREP_BLKS 8192    // NW*2048 / 256

__global__ void prep_cvt_kernel(const float* __restrict__ x,
                                const float* __restrict__ mask,
                                const float* __restrict__ rpb, const int* __restrict__ rel,
                                const float* __restrict__ qkv_w, const float* __restrict__ proj_w) {
    if (blockIdx.x < CVT_BLKS) {
        size_t t = (size_t)blockIdx.x * 256 + threadIdx.x;
        int lane = (int)(t & 31);
        size_t u = t >> 5;
        int k16 = (int)(u % K16S);
        int m16 = (int)(u / K16S);
        int r = lane >> 2, c = (lane & 3) << 1;
        const float* xp = x + (size_t)(m16 * 16) * CDIM + k16 * 16;
        float2 v00 = *(const float2*)(xp + (size_t)r * CDIM + c);
        float2 v10 = *(const float2*)(xp + (size_t)(r + 8) * CDIM + c);
        float2 v01 = *(const float2*)(xp + (size_t)r * CDIM + c + 8);
        float2 v11 = *(const float2*)(xp + (size_t)(r + 8) * CDIM + c + 8);
        uint4 o;
        o.x = h2u(v00.x, v00.y);
        o.y = h2u(v10.x, v10.y);
        o.z = h2u(v01.x, v01.y);
        o.w = h2u(v11.x, v11.y);
        *(uint4*)(g_xa + t * 4) = o;
        return;
    }
    int t = (blockIdx.x - CVT_BLKS) * 256 + threadIdx.x;
    if (t < NW * 2048) {
        int w = t >> 11, ij2 = t & 2047, i = ij2 >> 5, w32 = ij2 & 31;
        int j0 = 8 * (w32 & 7) + 2 * (w32 >> 3);
        float a = 0.f, b2 = 0.f;
        if (i < SEQ && j0 < SEQ)     a  = mask[(size_t)w * SEQ * SEQ + i * SEQ + j0] * LOG2E;
        if (i < SEQ && j0 + 1 < SEQ) b2 = mask[(size_t)w * SEQ * SEQ + i * SEQ + j0 + 1] * LOG2E;
        g_maskp_h[t] = h2u(a, b2);
    }
    if (t < HEADS * 2048) {
        int h = t >> 11, ij2 = t & 2047, i = ij2 >> 5, w32 = ij2 & 31;
        int j0 = 8 * (w32 & 7) + 2 * (w32 >> 3);
        float a = -30000.f, b2 = -30000.f;
        if (i < SEQ && j0 < SEQ)     a  = rpb[rel[i * SEQ + j0] * HEADS + h] * LOG2E;
        if (i < SEQ && j0 + 1 < SEQ) b2 = rpb[rel[i * SEQ + j0 + 1] * HEADS + h] * LOG2E;
        g_biasp_h[t] = h2u(a, b2);
    }
    // weights B-tiled fp16, paired-n8 layout: [n16][k16][lane][4]
    // words: {even-n8 (k,k+1), even-n8 (k+8,k+9), odd-n8 (k,k+1), odd-n8 (k+8,k+9)}
    if (t < (QKV_N / 16) * K16S * 32) {
        int lane = t & 31;
        int u = t >> 5;
        int k16 = u % K16S;
        int n16 = u / K16S;
        int kk = k16 * 16 + ((lane & 3) << 1);
        int nne = n16 * 16 + (lane >> 2);
        int nno = nne + 8;
        {
            uint4 o;
            o.x = h2u(qkv_w[(size_t)kk * QKV_N + nne],       qkv_w[(size_t)(kk + 1) * QKV_N + nne]);
            o.y = h2u(qkv_w[(size_t)(kk + 8) * QKV_N + nne], qkv_w[(size_t)(kk + 9) * QKV_N + nne]);
            o.z = h2u(qkv_w[(size_t)kk * QKV_N + nno],       qkv_w[(size_t)(kk + 1) * QKV_N + nno]);
            o.w = h2u(qkv_w[(size_t)(kk + 8) * QKV_N + nno], qkv_w[(size_t)(kk + 9) * QKV_N + nno]);
            *(uint4*)(g_wqkv_t + (size_t)t * 4) = o;
        }
        if (n16 < CDIM / 16) {
            uint4 o;
            o.x = h2u(proj_w[(size_t)kk * CDIM + nne],       proj_w[(size_t)(kk + 1) * CDIM + nne]);
            o.y = h2u(proj_w[(size_t)(kk + 8) * CDIM + nne], proj_w[(size_t)(kk + 9) * CDIM + nne]);
            o.z = h2u(proj_w[(size_t)kk * CDIM + nno],       proj_w[(size_t)(kk + 1) * CDIM + nno]);
            o.w = h2u(proj_w[(size_t)(kk + 8) * CDIM + nno], proj_w[(size_t)(kk + 9) * CDIM + nno]);
            *(uint4*)(g_wproj_t + (size_t)((n16 * K16S + k16) * 32 + lane) * 4) = o;
        }
    }
}

// ---------------------------------------------------------------------------
// GEMM fp16: BM=128, BN=128, BK=32, 256 threads (8 warps, 2m x 4n, warp 64x32),
// 4-stage cp.async, SINGLE barrier per chunk. Paired-n8 B loads (LDS.128).
// MODE 0 q-cols scaled by SCALE_F * LOG2E.
// ---------------------------------------------------------------------------
#define GSTAGE 16384
#define GSM_A(s) ((s) * GSTAGE)
#define GSM_B(s) ((s) * GSTAGE + 8192)
#define GEMM_DSMEM (4 * GSTAGE)

template <int MODE>
__global__ void __launch_bounds__(256, 2)
gemm_f16(const float* __restrict__ bias, float* __restrict__ C_out) {
    const uint32_t* A = (MODE == 0) ? g_xa : g_att_t;
    const uint32_t* W = (MODE == 0) ? g_wqkv_t : g_wproj_t;
    const int    Ntot = (MODE == 0) ? QKV_N : CDIM;

    extern __shared__ __align__(16) uint8_t sm[];

    const int tid  = threadIdx.x;
    const int warp = tid >> 5;
    const int lane = tid & 31;
    const int wm   = warp >> 2;          // 0..1 (64-row halves)
    const int wn   = warp & 3;           // 0..3 (32-col quarters)
    const int m16base = blockIdx.y * 8;
    const int n16base = blockIdx.x * 8;
    const int n0 = n16base * 16;

    auto load_chunk = [&](int s, int ch) {
#pragma unroll
        for (int it = 0; it < 2; ++it) {
            int idx = tid + it * 256;            // 0..511
            int u = idx >> 5, i = idx & 31;      // A unit 128 u32
            cp_async16(sm + GSM_A(s) + idx * 16,
                       A + (((size_t)(m16base + (u >> 1)) * K16S + ch * 2 + (u & 1)) * 32 + i) * 4);
        }
#pragma unroll
        for (int it = 0; it < 2; ++it) {
            int idx = tid + it * 256;            // 0..511
            int u = idx >> 5, i = idx & 31;      // B unit 128 u32 (n16 x k16)
            cp_async16(sm + GSM_B(s) + idx * 16,
                       W + (((size_t)(n16base + (u >> 1)) * K16S + ch * 2 + (u & 1)) * 32 + i) * 4);
        }
        cp_async_commit();
    };

    float acc[4][4][4];
#pragma unroll
    for (int i = 0; i < 4; ++i)
#pragma unroll
        for (int j = 0; j < 4; ++j)
#pragma unroll
            for (int q = 0; q < 4; ++q) acc[i][j][q] = 0.f;

    load_chunk(0, 0);
    load_chunk(1, 1);
    load_chunk(2, 2);

    const int NCH = K16S / 2;    // 12
    for (int ch = 0; ch < NCH; ++ch) {
        cp_async_wait<2>();       // chunk ch complete (groups ch+1, ch+2 may pend)
        __syncthreads();          // all warps done computing chunk ch-1
        if (ch + 3 < NCH) load_chunk((ch + 3) & 3, ch + 3);
        else              cp_async_commit();   // keep group accounting exact

        const int st = ch & 3;
        const uint32_t* smA = (const uint32_t*)(sm + GSM_A(st));
        const uint32_t* smB = (const uint32_t*)(sm + GSM_B(st));
#pragma unroll
        for (int kl = 0; kl < 2; ++kl) {
            uint4 a[4];
#pragma unroll
            for (int mt = 0; mt < 4; ++mt)
                a[mt] = *(const uint4*)&smA[(((wm * 4 + mt) * 2 + kl) * 32 + lane) * 4];
            uint4 bb[2];
#pragma unroll
            for (int nu = 0; nu < 2; ++nu)
                bb[nu] = *(const uint4*)&smB[(((wn * 2 + nu) * 2 + kl) * 32 + lane) * 4];
            uint32_t bfr[4][2];
#pragma unroll
            for (int nu = 0; nu < 2; ++nu) {
                bfr[nu * 2][0]     = bb[nu].x; bfr[nu * 2][1]     = bb[nu].y;
                bfr[nu * 2 + 1][0] = bb[nu].z; bfr[nu * 2 + 1][1] = bb[nu].w;
            }
#pragma unroll
            for (int mt = 0; mt < 4; ++mt)
#pragma unroll
                for (int nt = 0; nt < 4; ++nt)
                    mma_f16(acc[mt][nt], (const uint32_t*)&a[mt], bfr[nt]);
        }
    }

    const float qs = (MODE == 0 && n0 < CDIM) ? SCALE_F * LOG2E : 1.f;
    const int rbase = m16base * 16 + wm * 64 + (lane >> 2);
    const int cbase = n0 + wn * 32 + ((lane & 3) << 1);
    // nt order: 0=even n8 of n16#0, 1=odd n8 of n16#0, 2=even of #1, 3=odd of #1
#pragma unroll
    for (int mt = 0; mt < 4; ++mt) {
        int r = rbase + mt * 16;
#pragma unroll
        for (int nt = 0; nt < 4; ++nt) {
            int cc = cbase + (nt >> 1) * 16 + (nt & 1) * 8;
            float b0 = bias[cc], b1 = bias[cc + 1];
            const float* a4 = acc[mt][nt];
            if (MODE == 0) {
                g_qkv[(size_t)r * QKV_U + (cc >> 1)]       = h2u((a4[0] + b0) * qs, (a4[1] + b1) * qs);
                g_qkv[(size_t)(r + 8) * QKV_U + (cc >> 1)] = h2u((a4[2] + b0) * qs, (a4[3] + b1) * qs);
            } else {
                *(float2*)(C_out + (size_t)r * Ntot + cc)       = make_float2(a4[0] + b0, a4[1] + b1);
                *(float2*)(C_out + (size_t)(r + 8) * Ntot + cc) = make_float2(a4[2] + b0, a4[3] + b1);
            }
        }
    }
}

// ---------------------------------------------------------------------------
// Window attention (unchanged): one block per window, 12 heads,
// double-buffered cp.async, base-2 softmax, normalize-after-PV.
// ---------------------------------------------------------------------------
#define ATT_STAGE 3840   // q 1280 | k 1280 | v 1280 (u32), row stride 20 u32

__global__ void __launch_bounds__(128, 6)
attn_kernel() {
    const int b = blockIdx.x;

    __shared__ uint32_t sS[2][ATT_STAGE];

    const int tid  = threadIdx.x;
    const int warp = tid >> 5;
    const int lane = tid & 31;

    const uint32_t* gq = g_qkv + (size_t)b * SEQ * QKV_U;

    auto load_head = [&](int h, int buf) {
#pragma unroll
        for (int i = 0; i < 6; ++i) {
            int idx = tid + i * 128;                 // 0..767
            int which = idx >> 8;                    // 0=q 1=k 2=v
            int n = (idx >> 2) & 63;
            int part = idx & 3;
            int nc = (n < SEQ) ? n : 0;
            const uint32_t* src = gq + (size_t)nc * QKV_U + h * 16 + which * 192 + part * 4;
            cp_async16z(&sS[buf][which * 1280 + n * 20 + part * 4], src, (n < SEQ) ? 16u : 0u);
        }
        cp_async_commit();
    };

    load_head(0, 0);
    load_head(1, 1);

    const int r0 = warp * 16 + (lane >> 2);
    const int cq = lane & 3;
    const int c0 = cq << 1;
    const int li = lane & 7;
    const int l3 = (lane >> 3) & 1;
    const int l4 = lane >> 4;

    const uint32_t* mp = g_maskp_h + (size_t)(b & (NW - 1)) * 2048;

    for (int h = 0; h < HEADS; ++h) {
        const int cur = h & 1;
        cp_async_wait<1>();
        __syncthreads();

        const uint32_t qbase = sm2u(&sS[cur][0]);
        const uint32_t kbase = qbase + 1280 * 4;
        const uint32_t vbase = qbase + 2560 * 4;

        // ---- QK^T via ldmatrix ----
        float acc[8][4];
#pragma unroll
        for (int i = 0; i < 8; ++i)
#pragma unroll
            for (int j = 0; j < 4; ++j) acc[i][j] = 0.f;
#pragma unroll
        for (int s = 0; s < 2; ++s) {
            uint32_t a[4];
            ldsm_x4(a, qbase + (uint32_t)((warp * 16 + l3 * 8 + li) * 80 + (s * 16 + l4 * 8) * 2));
            uint32_t bf[4][4];
#pragma unroll
            for (int g = 0; g < 4; ++g)
                ldsm_x4(bf[g], kbase + (uint32_t)((g * 16 + l4 * 8 + li) * 80 + (s * 16 + l3 * 8) * 2));
#pragma unroll
            for (int g = 0; g < 4; ++g) {
                mma_f16(acc[2 * g],     a, &bf[g][0]);
                mma_f16(acc[2 * g + 1], a, &bf[g][2]);
            }
        }

        // ---- bias + mask (both LDG.128 from permuted fp16 tables) ----
        {
            const uint32_t* bp = g_biasp_h + h * 2048;
            uint4 b_lo0 = *(const uint4*)(bp + r0 * 32 + cq * 8);
            uint4 b_hi0 = *(const uint4*)(bp + r0 * 32 + cq * 8 + 4);
            uint4 b_lo1 = *(const uint4*)(bp + (r0 + 8) * 32 + cq * 8);
            uint4 b_hi1 = *(const uint4*)(bp + (r0 + 8) * 32 + cq * 8 + 4);
            uint4 m_lo0 = *(const uint4*)(mp + r0 * 32 + cq * 8);
            uint4 m_hi0 = *(const uint4*)(mp + r0 * 32 + cq * 8 + 4);
            uint4 m_lo1 = *(const uint4*)(mp + (r0 + 8) * 32 + cq * 8);
            uint4 m_hi1 = *(const uint4*)(mp + (r0 + 8) * 32 + cq * 8 + 4);
            const uint32_t* bw0 = (const uint32_t*)&b_lo0;
            const uint32_t* bw0h = (const uint32_t*)&b_hi0;
            const uint32_t* bw1 = (const uint32_t*)&b_lo1;
            const uint32_t* bw1h = (const uint32_t*)&b_hi1;
            const uint32_t* mw0 = (const uint32_t*)&m_lo0;
            const uint32_t* mw0h = (const uint32_t*)&m_hi0;
            const uint32_t* mw1 = (const uint32_t*)&m_lo1;
            const uint32_t* mw1h = (const uint32_t*)&m_hi1;
#pragma unroll
            for (int nt = 0; nt < 8; ++nt) {
                uint32_t bu0 = (nt < 4) ? bw0[nt] : bw0h[nt - 4];
                uint32_t bu1 = (nt < 4) ? bw1[nt] : bw1h[nt - 4];
                uint32_t mu0 = (nt < 4) ? mw0[nt] : mw0h[nt - 4];
                uint32_t mu1 = (nt < 4) ? mw1[nt] : mw1h[nt - 4];
                float2 fb0 = __half22float2(*(__half2*)&bu0);
                float2 fb1 = __half22float2(*(__half2*)&bu1);
                float2 fm0 = __half22float2(*(__half2*)&mu0);
                float2 fm1 = __half22float2(*(__half2*)&mu1);
                acc[nt][0] += fb0.x + fm0.x;
                acc[nt][1] += fb0.y + fm0.y;
                acc[nt][2] += fb1.x + fm1.x;
                acc[nt][3] += fb1.y + fm1.y;
            }
        }

        // ---- base-2 softmax, no max-subtraction; nt=7 is always padding ----
        float inv0, inv1;
        {
            float s0 = 0.f, s1 = 0.f;
#pragma unroll
            for (int nt = 0; nt < 7; ++nt) {
                acc[nt][0] = ex2(acc[nt][0]); s0 += acc[nt][0];
                acc[nt][1] = ex2(acc[nt][1]); s0 += acc[nt][1];
                acc[nt][2] = ex2(acc[nt][2]); s1 += acc[nt][2];
                acc[nt][3] = ex2(acc[nt][3]); s1 += acc[nt][3];
            }
            acc[7][0] = acc[7][1] = acc[7][2] = acc[7][3] = 0.f;
            s0 += __shfl_xor_sync(0xffffffffu, s0, 1);
            s0 += __shfl_xor_sync(0xffffffffu, s0, 2);
            s1 += __shfl_xor_sync(0xffffffffu, s1, 1);
            s1 += __shfl_xor_sync(0xffffffffu, s1, 2);
            inv0 = 1.f / s0;
            inv1 = 1.f / s1;
        }

        // ---- O = P V (P unnormalized, from registers); normalize after ----
        {
            float oacc[4][4];
#pragma unroll
            for (int i = 0; i < 4; ++i)
#pragma unroll
                for (int j = 0; j < 4; ++j) oacc[i][j] = 0.f;
#pragma unroll
            for (int s = 0; s < 4; ++s) {
                uint32_t a[4];
                a[0] = h2u(acc[2 * s][0],     acc[2 * s][1]);
                a[1] = h2u(acc[2 * s][2],     acc[2 * s][3]);
                a[2] = h2u(acc[2 * s + 1][0], acc[2 * s + 1][1]);
                a[3] = h2u(acc[2 * s + 1][2], acc[2 * s + 1][3]);
                uint32_t bf[2][4];
#pragma unroll
                for (int g = 0; g < 2; ++g)
                    ldsm_x4_t(bf[g], vbase + (uint32_t)((s * 16 + l3 * 8 + li) * 80 + (g * 16 + l4 * 8) * 2));
                mma_f16(oacc[0], a, &bf[0][0]);
                mma_f16(oacc[1], a, &bf[0][2]);
                mma_f16(oacc[2], a, &bf[1][0]);
                mma_f16(oacc[3], a, &bf[1][2]);
            }
#pragma unroll
            for (int nt = 0; nt < 4; ++nt) {
                int c = h * HDIM + nt * 8 + c0;
                if (r0 < SEQ)
                    g_att_t[a16_off(b * SEQ + r0, c)]     = h2u(oacc[nt][0] * inv0, oacc[nt][1] * inv0);
                if (r0 + 8 < SEQ)
                    g_att_t[a16_off(b * SEQ + r0 + 8, c)] = h2u(oacc[nt][2] * inv1, oacc[nt][3] * inv1);
            }
        }

        __syncthreads();   // all reads of cur buffer done before refill
        if (h + 2 < HEADS) load_head(h + 2, cur);
        else               cp_async_commit();
    }
}

// ---------------------------------------------------------------------------
// Launch
// ---------------------------------------------------------------------------
extern "C" void kernel_launch(void* const* d_in, const int* in_sizes, int n_in,
                              void* d_out, int out_size) {
    const float* x      = (const float*)d_in[0];
    const float* mask   = (const float*)d_in[1];
    const float* qkv_w  = (const float*)d_in[2];
    const float* qkv_b  = (const float*)d_in[3];
    const float* proj_w = (const float*)d_in[4];
    const float* proj_b = (const float*)d_in[5];
    const float* rpb    = (const float*)d_in[6];
    const int*   rel    = (const int*)d_in[7];
    float*       out    = (float*)d_out;

    cudaFuncSetAttribute(gemm_f16<0>, cudaFuncAttributeMaxDynamicSharedMemorySize, GEMM_DSMEM);
    cudaFuncSetAttribute(gemm_f16<1>, cudaFuncAttributeMaxDynamicSharedMemorySize, GEMM_DSMEM);

    // 0) merged prep (log2e-scaled fp16 tables + paired-n8 tiled weights) + x cvt
    prep_cvt_kernel<<<CVT_BLKS + PREP_BLKS, 256>>>(x, mask, rpb, rel, qkv_w, proj_w);
    // 1) QKV GEMM (q-cols scaled by SCALE_F*LOG2E)
    gemm_f16<0><<<dim3(QKV_N / 128, MROWS / 128), 256, GEMM_DSMEM>>>(qkv_b, nullptr);
    // 2) Attention (one block per window, 12 heads, double-buffered)
    attn_kernel<<<B_WIN, 128>>>();
    // 3) Proj GEMM
    gemm_f16<1><<<dim3(CDIM / 128, MROWS / 128), 256, GEMM_DSMEM>>>(proj_b, out);
}

// round 17
// speedup vs baseline: 1.5306x; 1.5306x over previous
#include <cuda_runtime.h>
#include <cuda_fp16.h>
#include <cstdint>

// Problem constants
#define B_WIN   4096
#define SEQ     49
#define NPAD    64
#define CDIM    384
#define HEADS   12
#define HDIM    32
#define NW      1024
#define MROWS   (B_WIN * SEQ)        // 200704
#define QKV_N   (3 * CDIM)           // 1152
#define QKV_U   (QKV_N / 2)          // 576 u32 per row
#define K16S    (CDIM / 16)          // 24 k16-subtiles
#define SCALE_F 0.17677669529663687f // 32^-0.5
#define LOG2E   1.4426950408889634f

// Scratch (static device globals)
__device__ uint32_t g_qkv[(size_t)MROWS * QKV_U];              // half2 rows (B_*N, 576)
__device__ uint32_t g_xa[(size_t)(MROWS / 16) * K16S * 128];   // x, A-tiled fp16
__device__ uint32_t g_att_t[(size_t)(MROWS / 16) * K16S * 128];// attn out, A-tiled fp16
__device__ uint32_t g_wqkv_t[(QKV_N / 8) * K16S * 64];         // B-tiled fp16 [n8][k16][lane][2]
__device__ uint32_t g_wproj_t[(CDIM / 8) * K16S * 64];
__device__ uint32_t g_biasp_h[HEADS * 2048];                   // fp16 bias*log2e, permuted, pad=-30000
__device__ uint32_t g_maskp_h[NW * 2048];                      // fp16 mask*log2e, permuted, pad=0

// ---------------------------------------------------------------------------
// Helpers
// ---------------------------------------------------------------------------
__device__ __forceinline__ uint32_t h2u(float a, float b) {
    __half2 h = __floats2half2_rn(a, b);
    return *(uint32_t*)&h;
}
__device__ __forceinline__ float ex2(float x) {
    float y;
    asm("ex2.approx.f32 %0, %1;" : "=f"(y) : "f"(x));
    return y;
}

__device__ __forceinline__ void mma_f16(float* c, const uint32_t* a, const uint32_t* b) {
    asm volatile(
        "mma.sync.aligned.m16n8k16.row.col.f32.f16.f16.f32 "
        "{%0,%1,%2,%3}, {%4,%5,%6,%7}, {%8,%9}, {%0,%1,%2,%3};\n"
        : "+f"(c[0]), "+f"(c[1]), "+f"(c[2]), "+f"(c[3])
        : "r"(a[0]), "r"(a[1]), "r"(a[2]), "r"(a[3]), "r"(b[0]), "r"(b[1]));
}

__device__ __forceinline__ void ldsm_x4(uint32_t* r, uint32_t addr) {
    asm volatile("ldmatrix.sync.aligned.m8n8.x4.shared.b16 {%0,%1,%2,%3}, [%4];"
                 : "=r"(r[0]), "=r"(r[1]), "=r"(r[2]), "=r"(r[3]) : "r"(addr));
}
__device__ __forceinline__ void ldsm_x4_t(uint32_t* r, uint32_t addr) {
    asm volatile("ldmatrix.sync.aligned.m8n8.x4.trans.shared.b16 {%0,%1,%2,%3}, [%4];"
                 : "=r"(r[0]), "=r"(r[1]), "=r"(r[2]), "=r"(r[3]) : "r"(addr));
}
__device__ __forceinline__ uint32_t sm2u(const void* p) {
    return (uint32_t)__cvta_generic_to_shared(p);
}

__device__ __forceinline__ void cp_async16(void* smem_dst, const void* gmem_src) {
    uint32_t s = (uint32_t)__cvta_generic_to_shared(smem_dst);
    asm volatile("cp.async.cg.shared.global [%0], [%1], 16;\n" :: "r"(s), "l"(gmem_src));
}
__device__ __forceinline__ void cp_async16z(void* smem_dst, const void* gmem_src, uint32_t src_sz) {
    uint32_t s = (uint32_t)__cvta_generic_to_shared(smem_dst);
    asm volatile("cp.async.cg.shared.global [%0], [%1], 16, %2;\n" :: "r"(s), "l"(gmem_src), "r"(src_sz));
}
__device__ __forceinline__ void cp_async_commit() {
    asm volatile("cp.async.commit_group;\n" ::: "memory");
}
template <int N>
__device__ __forceinline__ void cp_async_wait() {
    asm volatile("cp.async.wait_group %0;\n" :: "n"(N) : "memory");
}

// A-tiled fp16 u32 index for element pair (m, c..c+1), c even, K=384
__device__ __forceinline__ size_t a16_off(int m, int c) {
    int m16 = m >> 4, rr = m & 15, k16 = c >> 4, kc = c & 15;
    int lane = ((rr & 7) << 2) | ((kc & 7) >> 1);
    int w = (rr >> 3) | ((kc >> 3) << 1);
    return (((size_t)m16 * K16S + k16) * 32 + lane) * 4 + w;
}

// ---------------------------------------------------------------------------
// Merged cvt_x + prep (block-range partitioned) — identical to R14
// ---------------------------------------------------------------------------
#define CVT_BLKS 37632    // (MROWS/16)*K16S*32 / 256
#define PREP_BLKS 8192    // NW*2048 / 256

__global__ void prep_cvt_kernel(const float* __restrict__ x,
                                const float* __restrict__ mask,
                                const float* __restrict__ rpb, const int* __restrict__ rel,
                                const float* __restrict__ qkv_w, const float* __restrict__ proj_w) {
    if (blockIdx.x < CVT_BLKS) {
        size_t t = (size_t)blockIdx.x * 256 + threadIdx.x;
        int lane = (int)(t & 31);
        size_t u = t >> 5;
        int k16 = (int)(u % K16S);
        int m16 = (int)(u / K16S);
        int r = lane >> 2, c = (lane & 3) << 1;
        const float* xp = x + (size_t)(m16 * 16) * CDIM + k16 * 16;
        float2 v00 = *(const float2*)(xp + (size_t)r * CDIM + c);
        float2 v10 = *(const float2*)(xp + (size_t)(r + 8) * CDIM + c);
        float2 v01 = *(const float2*)(xp + (size_t)r * CDIM + c + 8);
        float2 v11 = *(const float2*)(xp + (size_t)(r + 8) * CDIM + c + 8);
        uint4 o;
        o.x = h2u(v00.x, v00.y);
        o.y = h2u(v10.x, v10.y);
        o.z = h2u(v01.x, v01.y);
        o.w = h2u(v11.x, v11.y);
        *(uint4*)(g_xa + t * 4) = o;
        return;
    }
    int t = (blockIdx.x - CVT_BLKS) * 256 + threadIdx.x;
    if (t < NW * 2048) {
        int w = t >> 11, ij2 = t & 2047, i = ij2 >> 5, w32 = ij2 & 31;
        int j0 = 8 * (w32 & 7) + 2 * (w32 >> 3);
        float a = 0.f, b2 = 0.f;
        if (i < SEQ && j0 < SEQ)     a  = mask[(size_t)w * SEQ * SEQ + i * SEQ + j0] * LOG2E;
        if (i < SEQ && j0 + 1 < SEQ) b2 = mask[(size_t)w * SEQ * SEQ + i * SEQ + j0 + 1] * LOG2E;
        g_maskp_h[t] = h2u(a, b2);
    }
    if (t < HEADS * 2048) {
        int h = t >> 11, ij2 = t & 2047, i = ij2 >> 5, w32 = ij2 & 31;
        int j0 = 8 * (w32 & 7) + 2 * (w32 >> 3);
        float a = -30000.f, b2 = -30000.f;
        if (i < SEQ && j0 < SEQ)     a  = rpb[rel[i * SEQ + j0] * HEADS + h] * LOG2E;
        if (i < SEQ && j0 + 1 < SEQ) b2 = rpb[rel[i * SEQ + j0 + 1] * HEADS + h] * LOG2E;
        g_biasp_h[t] = h2u(a, b2);
    }
    if (t < (QKV_N / 8) * K16S * 32) {
        int lane = t & 31;
        int u = t >> 5;
        int k16 = u % K16S;
        int n8 = u / K16S;
        int kk = k16 * 16 + ((lane & 3) << 1);
        int nn = n8 * 8 + (lane >> 2);
        {
            uint2 o;
            o.x = h2u(qkv_w[(size_t)kk * QKV_N + nn],       qkv_w[(size_t)(kk + 1) * QKV_N + nn]);
            o.y = h2u(qkv_w[(size_t)(kk + 8) * QKV_N + nn], qkv_w[(size_t)(kk + 9) * QKV_N + nn]);
            *(uint2*)(g_wqkv_t + (size_t)t * 2) = o;
        }
        if (n8 < CDIM / 8) {
            uint2 o;
            o.x = h2u(proj_w[(size_t)kk * CDIM + nn],       proj_w[(size_t)(kk + 1) * CDIM + nn]);
            o.y = h2u(proj_w[(size_t)(kk + 8) * CDIM + nn], proj_w[(size_t)(kk + 9) * CDIM + nn]);
            *(uint2*)(g_wproj_t + (size_t)((n8 * K16S + k16) * 32 + lane) * 2) = o;
        }
    }
}

// ---------------------------------------------------------------------------
// GEMM fp16: BM=128, BN=128, BK=64 (4 k16-steps/chunk), 256 threads
// (8 warps, 2m x 4n, warp 64x32), 3-stage cp.async, R14 double-barrier
// structure. NCH=6 halves barrier count vs BK=32.
// MODE 0 q-cols scaled by SCALE_F * LOG2E.
// ---------------------------------------------------------------------------
#define GSTAGE 32768
#define GSM_A(s) ((s) * GSTAGE)
#define GSM_B(s) ((s) * GSTAGE + 16384)
#define GEMM_DSMEM (3 * GSTAGE)

template <int MODE>
__global__ void __launch_bounds__(256, 2)
gemm_f16(const float* __restrict__ bias, float* __restrict__ C_out) {
    const uint32_t* A = (MODE == 0) ? g_xa : g_att_t;
    const uint32_t* W = (MODE == 0) ? g_wqkv_t : g_wproj_t;
    const int    Ntot = (MODE == 0) ? QKV_N : CDIM;

    extern __shared__ __align__(16) uint8_t sm[];

    const int tid  = threadIdx.x;
    const int warp = tid >> 5;
    const int lane = tid & 31;
    const int wm   = warp >> 2;          // 0..1 (64-row halves)
    const int wn   = warp & 3;           // 0..3 (32-col quarters)
    const int m16base = blockIdx.y * 8;
    const int n8base  = blockIdx.x * 16;
    const int n0 = n8base * 8;

    auto load_chunk = [&](int s, int ch) {
        // A: 8 m16 x 4 k16 units of 128 u32 (512B)  -> 1024 x 16B
#pragma unroll
        for (int it = 0; it < 4; ++it) {
            int idx = tid + it * 256;            // 0..1023
            int u = idx >> 5, i = idx & 31;
            cp_async16(sm + GSM_A(s) + idx * 16,
                       A + (((size_t)(m16base + (u >> 2)) * K16S + ch * 4 + (u & 3)) * 32 + i) * 4);
        }
        // B: 16 n8 x 4 k16 units of 64 u32 (256B) -> 1024 x 16B
#pragma unroll
        for (int it = 0; it < 4; ++it) {
            int idx = tid + it * 256;
            int u = idx >> 4, i16 = idx & 15;
            cp_async16(sm + GSM_B(s) + idx * 16,
                       W + ((size_t)(n8base + (u >> 2)) * K16S + ch * 4 + (u & 3)) * 64 + i16 * 4);
        }
        cp_async_commit();
    };

    float acc[4][4][4];
#pragma unroll
    for (int i = 0; i < 4; ++i)
#pragma unroll
        for (int j = 0; j < 4; ++j)
#pragma unroll
            for (int q = 0; q < 4; ++q) acc[i][j][q] = 0.f;

    load_chunk(0, 0);
    load_chunk(1, 1);

    const int NCH = K16S / 4;    // 6
    for (int ch = 0; ch < NCH; ++ch) {
        if (ch + 2 < NCH) load_chunk((ch + 2) % 3, ch + 2);
        else              cp_async_commit();
        cp_async_wait<2>();
        __syncthreads();

        const uint32_t* smA = (const uint32_t*)(sm + GSM_A(ch % 3));
        const uint32_t* smB = (const uint32_t*)(sm + GSM_B(ch % 3));
#pragma unroll
        for (int kl = 0; kl < 4; ++kl) {
            uint4 a[4];
#pragma unroll
            for (int mt = 0; mt < 4; ++mt)
                a[mt] = *(const uint4*)&smA[(((wm * 4 + mt) * 4 + kl) * 32 + lane) * 4];
            uint2 b[4];
#pragma unroll
            for (int nt = 0; nt < 4; ++nt)
                b[nt] = *(const uint2*)&smB[(((wn * 4 + nt) * 4 + kl) * 32 + lane) * 2];
#pragma unroll
            for (int mt = 0; mt < 4; ++mt)
#pragma unroll
                for (int nt = 0; nt < 4; ++nt)
                    mma_f16(acc[mt][nt], (const uint32_t*)&a[mt], (const uint32_t*)&b[nt]);
        }
        __syncthreads();
    }

    const float qs = (MODE == 0 && n0 < CDIM) ? SCALE_F * LOG2E : 1.f;
    const int rbase = m16base * 16 + wm * 64 + (lane >> 2);
    const int cbase = n0 + wn * 32 + ((lane & 3) << 1);
#pragma unroll
    for (int mt = 0; mt < 4; ++mt) {
        int r = rbase + mt * 16;
#pragma unroll
        for (int nt = 0; nt < 4; ++nt) {
            int cc = cbase + nt * 8;
            float b0 = bias[cc], b1 = bias[cc + 1];
            const float* a4 = acc[mt][nt];
            if (MODE == 0) {
                g_qkv[(size_t)r * QKV_U + (cc >> 1)]       = h2u((a4[0] + b0) * qs, (a4[1] + b1) * qs);
                g_qkv[(size_t)(r + 8) * QKV_U + (cc >> 1)] = h2u((a4[2] + b0) * qs, (a4[3] + b1) * qs);
            } else {
                *(float2*)(C_out + (size_t)r * Ntot + cc)       = make_float2(a4[0] + b0, a4[1] + b1);
                *(float2*)(C_out + (size_t)(r + 8) * Ntot + cc) = make_float2(a4[2] + b0, a4[3] + b1);
            }
        }
    }
}

// ---------------------------------------------------------------------------
// Window attention (unchanged): one block per window, 12 heads,
// double-buffered cp.async, base-2 softmax, normalize-after-PV.
// ---------------------------------------------------------------------------
#define ATT_STAGE 3840   // q 1280 | k 1280 | v 1280 (u32), row stride 20 u32

__global__ void __launch_bounds__(128, 6)
attn_kernel() {
    const int b = blockIdx.x;

    __shared__ uint32_t sS[2][ATT_STAGE];

    const int tid  = threadIdx.x;
    const int warp = tid >> 5;
    const int lane = tid & 31;

    const uint32_t* gq = g_qkv + (size_t)b * SEQ * QKV_U;

    auto load_head = [&](int h, int buf) {
#pragma unroll
        for (int i = 0; i < 6; ++i) {
            int idx = tid + i * 128;                 // 0..767
            int which = idx >> 8;                    // 0=q 1=k 2=v
            int n = (idx >> 2) & 63;
            int part = idx & 3;
            int nc = (n < SEQ) ? n : 0;
            const uint32_t* src = gq + (size_t)nc * QKV_U + h * 16 + which * 192 + part * 4;
            cp_async16z(&sS[buf][which * 1280 + n * 20 + part * 4], src, (n < SEQ) ? 16u : 0u);
        }
        cp_async_commit();
    };

    load_head(0, 0);
    load_head(1, 1);

    const int r0 = warp * 16 + (lane >> 2);
    const int cq = lane & 3;
    const int c0 = cq << 1;
    const int li = lane & 7;
    const int l3 = (lane >> 3) & 1;
    const int l4 = lane >> 4;

    const uint32_t* mp = g_maskp_h + (size_t)(b & (NW - 1)) * 2048;

    for (int h = 0; h < HEADS; ++h) {
        const int cur = h & 1;
        cp_async_wait<1>();
        __syncthreads();

        const uint32_t qbase = sm2u(&sS[cur][0]);
        const uint32_t kbase = qbase + 1280 * 4;
        const uint32_t vbase = qbase + 2560 * 4;

        // ---- QK^T via ldmatrix ----
        float acc[8][4];
#pragma unroll
        for (int i = 0; i < 8; ++i)
#pragma unroll
            for (int j = 0; j < 4; ++j) acc[i][j] = 0.f;
#pragma unroll
        for (int s = 0; s < 2; ++s) {
            uint32_t a[4];
            ldsm_x4(a, qbase + (uint32_t)((warp * 16 + l3 * 8 + li) * 80 + (s * 16 + l4 * 8) * 2));
            uint32_t bf[4][4];
#pragma unroll
            for (int g = 0; g < 4; ++g)
                ldsm_x4(bf[g], kbase + (uint32_t)((g * 16 + l4 * 8 + li) * 80 + (s * 16 + l3 * 8) * 2));
#pragma unroll
            for (int g = 0; g < 4; ++g) {
                mma_f16(acc[2 * g],     a, &bf[g][0]);
                mma_f16(acc[2 * g + 1], a, &bf[g][2]);
            }
        }

        // ---- bias + mask (both LDG.128 from permuted fp16 tables) ----
        {
            const uint32_t* bp = g_biasp_h + h * 2048;
            uint4 b_lo0 = *(const uint4*)(bp + r0 * 32 + cq * 8);
            uint4 b_hi0 = *(const uint4*)(bp + r0 * 32 + cq * 8 + 4);
            uint4 b_lo1 = *(const uint4*)(bp + (r0 + 8) * 32 + cq * 8);
            uint4 b_hi1 = *(const uint4*)(bp + (r0 + 8) * 32 + cq * 8 + 4);
            uint4 m_lo0 = *(const uint4*)(mp + r0 * 32 + cq * 8);
            uint4 m_hi0 = *(const uint4*)(mp + r0 * 32 + cq * 8 + 4);
            uint4 m_lo1 = *(const uint4*)(mp + (r0 + 8) * 32 + cq * 8);
            uint4 m_hi1 = *(const uint4*)(mp + (r0 + 8) * 32 + cq * 8 + 4);
            const uint32_t* bw0 = (const uint32_t*)&b_lo0;
            const uint32_t* bw0h = (const uint32_t*)&b_hi0;
            const uint32_t* bw1 = (const uint32_t*)&b_lo1;
            const uint32_t* bw1h = (const uint32_t*)&b_hi1;
            const uint32_t* mw0 = (const uint32_t*)&m_lo0;
            const uint32_t* mw0h = (const uint32_t*)&m_hi0;
            const uint32_t* mw1 = (const uint32_t*)&m_lo1;
            const uint32_t* mw1h = (const uint32_t*)&m_hi1;
#pragma unroll
            for (int nt = 0; nt < 8; ++nt) {
                uint32_t bu0 = (nt < 4) ? bw0[nt] : bw0h[nt - 4];
                uint32_t bu1 = (nt < 4) ? bw1[nt] : bw1h[nt - 4];
                uint32_t mu0 = (nt < 4) ? mw0[nt] : mw0h[nt - 4];
                uint32_t mu1 = (nt < 4) ? mw1[nt] : mw1h[nt - 4];
                float2 fb0 = __half22float2(*(__half2*)&bu0);
                float2 fb1 = __half22float2(*(__half2*)&bu1);
                float2 fm0 = __half22float2(*(__half2*)&mu0);
                float2 fm1 = __half22float2(*(__half2*)&mu1);
                acc[nt][0] += fb0.x + fm0.x;
                acc[nt][1] += fb0.y + fm0.y;
                acc[nt][2] += fb1.x + fm1.x;
                acc[nt][3] += fb1.y + fm1.y;
            }
        }

        // ---- base-2 softmax, no max-subtraction; nt=7 is always padding ----
        float inv0, inv1;
        {
            float s0 = 0.f, s1 = 0.f;
#pragma unroll
            for (int nt = 0; nt < 7; ++nt) {
                acc[nt][0] = ex2(acc[nt][0]); s0 += acc[nt][0];
                acc[nt][1] = ex2(acc[nt][1]); s0 += acc[nt][1];
                acc[nt][2] = ex2(acc[nt][2]); s1 += acc[nt][2];
                acc[nt][3] = ex2(acc[nt][3]); s1 += acc[nt][3];
            }
            acc[7][0] = acc[7][1] = acc[7][2] = acc[7][3] = 0.f;
            s0 += __shfl_xor_sync(0xffffffffu, s0, 1);
            s0 += __shfl_xor_sync(0xffffffffu, s0, 2);
            s1 += __shfl_xor_sync(0xffffffffu, s1, 1);
            s1 += __shfl_xor_sync(0xffffffffu, s1, 2);
            inv0 = 1.f / s0;
            inv1 = 1.f / s1;
        }

        // ---- O = P V (P unnormalized, from registers); normalize after ----
        {
            float oacc[4][4];
#pragma unroll
            for (int i = 0; i < 4; ++i)
#pragma unroll
                for (int j = 0; j < 4; ++j) oacc[i][j] = 0.f;
#pragma unroll
            for (int s = 0; s < 4; ++s) {
                uint32_t a[4];
                a[0] = h2u(acc[2 * s][0],     acc[2 * s][1]);
                a[1] = h2u(acc[2 * s][2],     acc[2 * s][3]);
                a[2] = h2u(acc[2 * s + 1][0], acc[2 * s + 1][1]);
                a[3] = h2u(acc[2 * s + 1][2], acc[2 * s + 1][3]);
                uint32_t bf[2][4];
#pragma unroll
                for (int g = 0; g < 2; ++g)
                    ldsm_x4_t(bf[g], vbase + (uint32_t)((s * 16 + l3 * 8 + li) * 80 + (g * 16 + l4 * 8) * 2));
                mma_f16(oacc[0], a, &bf[0][0]);
                mma_f16(oacc[1], a, &bf[0][2]);
                mma_f16(oacc[2], a, &bf[1][0]);
                mma_f16(oacc[3], a, &bf[1][2]);
            }
#pragma unroll
            for (int nt = 0; nt < 4; ++nt) {
                int c = h * HDIM + nt * 8 + c0;
                if (r0 < SEQ)
                    g_att_t[a16_off(b * SEQ + r0, c)]     = h2u(oacc[nt][0] * inv0, oacc[nt][1] * inv0);
                if (r0 + 8 < SEQ)
                    g_att_t[a16_off(b * SEQ + r0 + 8, c)] = h2u(oacc[nt][2] * inv1, oacc[nt][3] * inv1);
            }
        }

        __syncthreads();   // all reads of cur buffer done before refill
        if (h + 2 < HEADS) load_head(h + 2, cur);
        else               cp_async_commit();
    }
}

// ---------------------------------------------------------------------------
// Launch
// ---------------------------------------------------------------------------
extern "C" void kernel_launch(void* const* d_in, const int* in_sizes, int n_in,
                              void* d_out, int out_size) {
    const float* x      = (const float*)d_in[0];
    const float* mask   = (const float*)d_in[1];
    const float* qkv_w  = (const float*)d_in[2];
    const float* qkv_b  = (const float*)d_in[3];
    const float* proj_w = (const float*)d_in[4];
    const float* proj_b = (const float*)d_in[5];
    const float* rpb    = (const float*)d_in[6];
    const int*   rel    = (const int*)d_in[7];
    float*       out    = (float*)d_out;

    cudaFuncSetAttribute(gemm_f16<0>, cudaFuncAttributeMaxDynamicSharedMemorySize, GEMM_DSMEM);
    cudaFuncSetAttribute(gemm_f16<1>, cudaFuncAttributeMaxDynamicSharedMemorySize, GEMM_DSMEM);

    // 0) merged prep (log2e-scaled fp16 tables + tiled weights) + x cvt
    prep_cvt_kernel<<<CVT_BLKS + PREP_BLKS, 256>>>(x, mask, rpb, rel, qkv_w, proj_w);
    // 1) QKV GEMM (q-cols scaled by SCALE_F*LOG2E)
    gemm_f16<0><<<dim3(QKV_N / 128, MROWS / 128), 256, GEMM_DSMEM>>>(qkv_b, nullptr);
    // 2) Attention (one block per window, 12 heads, double-buffered)
    attn_kernel<<<B_WIN, 128>>>();
    // 3) Proj GEMM
    gemm_f16<1><<<dim3(CDIM / 128, MROWS / 128), 256, GEMM_DSMEM>>>(proj_b, out);
}